// round 9
// baseline (speedup 1.0000x reference)
#include <cuda_runtime.h>
#include <cstdint>
#include <math.h>

// Pacemaker: OU + Bernoulli spikes, bit-matching JAX threefry2x32
// (partitionable) + XLA erfinv. T=16384, N=8192, out f32 [T,N].
//
// R8: single producer-consumer mega-kernel.
//   roles by blockIdx: [scan x256] then groups of [noise tiles chunk c | spike
//   tiles chunk c-2]. Flags: g_ncnt[c] (noise done), g_scnt[c] (scan done).
//   release/acquire via red.release.gpu / ld.acquire.gpu.
//   TF sub-round adds forced onto the FMA pipe (mad.lo.u32 with opaque 1).

#define T_STEPS 16384
#define N_NEUR  8192
#define NCHUNK  512                    // T / 32
#define SCAN_BLOCKS 256                // N / 32

__device__ uint2 g_kn[T_STEPS];
__device__ uint2 g_kb[T_STEPS];
__device__ __align__(16) float g_noise[(size_t)T_STEPS * N_NEUR];
__device__ int g_ncnt[NCHUNK];
__device__ int g_scnt[NCHUNK];
__device__ int g_one;                  // runtime 1, opaque to ptxas

// ---------------------------------------------------------------------------
// sync helpers
// ---------------------------------------------------------------------------
__device__ __forceinline__ int ld_acq(const int* p) {
  int v;
  asm volatile("ld.acquire.gpu.global.b32 %0, [%1];" : "=r"(v) : "l"(p) : "memory");
  return v;
}
__device__ __forceinline__ void red_rel(int* p) {
  asm volatile("red.release.gpu.global.add.s32 [%0], %1;" :: "l"(p), "r"(1) : "memory");
}
__device__ __forceinline__ void wait_cnt(const int* p, int target) {
  unsigned ns = 64;
  while (ld_acq(p) < target) { __nanosleep(ns); if (ns < 4096) ns <<= 1; }
}

// ---------------------------------------------------------------------------
// threefry2x32 (20 rounds) — identical to jax._src.prng.threefry2x32.
// Sub-round adds emitted as IMAD (fma pipe) via opaque multiplier `one`.
// ---------------------------------------------------------------------------
__device__ __forceinline__ uint32_t addx(uint32_t a, uint32_t b, uint32_t one) {
  uint32_t r;
  asm("mad.lo.u32 %0, %1, %2, %3;" : "=r"(r) : "r"(a), "r"(one), "r"(b));
  return r;
}
__device__ __forceinline__ void tf_round4(uint32_t& x0, uint32_t& x1,
                                          int r0, int r1, int r2, int r3,
                                          uint32_t one) {
  x0 = addx(x0, x1, one); x1 = __funnelshift_l(x1, x1, r0); x1 ^= x0;
  x0 = addx(x0, x1, one); x1 = __funnelshift_l(x1, x1, r1); x1 ^= x0;
  x0 = addx(x0, x1, one); x1 = __funnelshift_l(x1, x1, r2); x1 ^= x0;
  x0 = addx(x0, x1, one); x1 = __funnelshift_l(x1, x1, r3); x1 ^= x0;
}
__device__ __forceinline__ uint2 threefry2x32(uint32_t k0, uint32_t k1,
                                              uint32_t x0, uint32_t x1,
                                              uint32_t one) {
  uint32_t ks2 = k0 ^ k1 ^ 0x1BD11BDAu;
  x0 += k0; x1 += k1;
  tf_round4(x0, x1, 13, 15, 26, 6,  one); x0 += k1;  x1 += ks2 + 1u;
  tf_round4(x0, x1, 17, 29, 16, 24, one); x0 += ks2; x1 += k0  + 2u;
  tf_round4(x0, x1, 13, 15, 26, 6,  one); x0 += k0;  x1 += k1  + 3u;
  tf_round4(x0, x1, 17, 29, 16, 24, one); x0 += k1;  x1 += ks2 + 4u;
  tf_round4(x0, x1, 13, 15, 26, 6,  one); x0 += ks2; x1 += k0  + 5u;
  return make_uint2(x0, x1);
}

// uniform [0,1): bitcast((bits>>9)|0x3f800000) - 1  (exact, matches jax)
__device__ __forceinline__ float u01_from_bits(uint32_t bits) {
  return __fsub_rn(__uint_as_float((bits >> 9) | 0x3f800000u), 1.0f);
}

// XLA ErfInv (f32, Giles). Separate mul/add (XLA does not form FMAs).
__device__ __forceinline__ float erfinv_xla(float x) {
  float w = -log1pf(-__fmul_rn(x, x));
  float p;
  if (w < 5.0f) {
    w = __fadd_rn(w, -2.5f);
    p = 2.81022636e-08f;
    p = __fadd_rn(3.43273939e-07f,  __fmul_rn(p, w));
    p = __fadd_rn(-3.5233877e-06f,  __fmul_rn(p, w));
    p = __fadd_rn(-4.39150654e-06f, __fmul_rn(p, w));
    p = __fadd_rn(0.00021858087f,   __fmul_rn(p, w));
    p = __fadd_rn(-0.00125372503f,  __fmul_rn(p, w));
    p = __fadd_rn(-0.00417768164f,  __fmul_rn(p, w));
    p = __fadd_rn(0.246640727f,     __fmul_rn(p, w));
    p = __fadd_rn(1.50140941f,      __fmul_rn(p, w));
  } else {
    w = __fadd_rn(__fsqrt_rn(w), -3.0f);
    p = -0.000200214257f;
    p = __fadd_rn(0.000100950558f,  __fmul_rn(p, w));
    p = __fadd_rn(0.00134934322f,   __fmul_rn(p, w));
    p = __fadd_rn(-0.00367342844f,  __fmul_rn(p, w));
    p = __fadd_rn(0.00573950773f,   __fmul_rn(p, w));
    p = __fadd_rn(-0.0076224613f,   __fmul_rn(p, w));
    p = __fadd_rn(0.00943887047f,   __fmul_rn(p, w));
    p = __fadd_rn(1.00167406f,      __fmul_rn(p, w));
    p = __fadd_rn(2.83297682f,      __fmul_rn(p, w));
  }
  return __fmul_rn(p, x);
}

// ---------------------------------------------------------------------------
// K0: per-step keys + flag reset (runs before k_mega each replay).
// split(key(0),T)[t] = TF((0,0),(0,t)); kn = TF(kt,(0,0)); kb = TF(kt,(0,1))
// ---------------------------------------------------------------------------
__global__ void __launch_bounds__(256) k_keys() {
  int t = blockIdx.x * blockDim.x + threadIdx.x;
  if (t < NCHUNK) { g_ncnt[t] = 0; g_scnt[t] = 0; }
  if (t == 0) g_one = 1;
  if (t >= T_STEPS) return;
  uint2 kt = threefry2x32(0u, 0u, 0u, (uint32_t)t, 1u);
  g_kn[t] = threefry2x32(kt.x, kt.y, 0u, 0u, 1u);
  g_kb[t] = threefry2x32(kt.x, kt.y, 0u, 1u, 1u);
}

// ---------------------------------------------------------------------------
// K1: mega kernel.
//  bid [0,256): scan (warp0 only). Polls g_ncnt[c]==256, runs FP-exact OU
//    chain on 32 t-major rows, writes x to out, releases g_scnt[c].
//  bid >= 256: g = bid-256; cg = g>>9; h = g&511.
//    h <  256 & cg < 512 : noise tile (chunk cg, tile h)   [8t x 128i]
//    h >= 256 & cg >= 2  : spike tile (chunk cg-2, tile h-256) [32t x 32i]
// ---------------------------------------------------------------------------
__global__ void __launch_bounds__(256) k_mega(const float* __restrict__ state,
                                              float* __restrict__ out) {
  const unsigned bid = blockIdx.x;

  if (bid < SCAN_BLOCKS) {
    // ---- scan role ----
    if (threadIdx.x >= 32) return;
    const int lane = threadIdx.x;
    const int i = (int)bid * 32 + lane;
    float x = state[i];
    const float DT_F = 0.001f;

    for (int c = 0; c < NCHUNK; c++) {
      wait_cnt(&g_ncnt[c], 256);
      const float* src = g_noise + (size_t)c * 32 * N_NEUR + i;
      float*       dst = out     + (size_t)c * 32 * N_NEUR + i;
      float n[32];
#pragma unroll
      for (int k = 0; k < 32; k++) n[k] = __ldcg(src + (size_t)k * N_NEUR);
#pragma unroll
      for (int k = 0; k < 32; k++) {
        x = __fadd_rn(__fsub_rn(x, __fmul_rn(x, DT_F)), n[k]);
        dst[(size_t)k * N_NEUR] = x;
      }
      __threadfence();
      __syncwarp();
      if (lane == 0) red_rel(&g_scnt[c]);
    }
    return;
  }

  const uint32_t one = (uint32_t)g_one;   // runtime 1 -> IMAD stays IMAD
  const unsigned g  = bid - SCAN_BLOCKS;
  const int cg = (int)(g >> 9);
  const int h  = (int)(g & 511);

  if (h < 256) {
    // ---- noise tile: chunk cg, 8t x 128i ----
    if (cg >= NCHUNK) return;
    const int t  = cg * 32 + (h >> 6) * 8 + (threadIdx.x >> 5);
    const int i0 = (h & 63) * 128 + (threadIdx.x & 31) * 4;
    uint2 kn = g_kn[t];                        // warp-uniform

    const float LO  = __uint_as_float(0xBF7FFFFFu);   // nextafter(-1, 0)
    const float SQ2 = __uint_as_float(0x3FB504F3u);   // float(sqrt(2))
    const float NS  = (float)(0.6 * sqrt(0.001));     // sigma * sqrt(dt)

    float tmp[4];
#pragma unroll
    for (int jx = 0; jx < 4; jx++) {
      uint2 r = threefry2x32(kn.x, kn.y, 0u, (uint32_t)(i0 + jx), one);
      float f = u01_from_bits(r.x ^ r.y);
      float u = __fadd_rn(__fmul_rn(f, 2.0f), LO);
      u = fmaxf(LO, u);
      tmp[jx] = __fmul_rn(__fmul_rn(SQ2, erfinv_xla(u)), NS);
    }
    float4 o; o.x = tmp[0]; o.y = tmp[1]; o.z = tmp[2]; o.w = tmp[3];
    *reinterpret_cast<float4*>(g_noise + (size_t)t * N_NEUR + i0) = o;

    __syncthreads();
    if (threadIdx.x == 0) { __threadfence(); red_rel(&g_ncnt[cg]); }
    return;
  }

  // ---- spike tile: chunk cg-2, 32t x 32i ----
  {
    const int c = cg - 2;
    if (c < 0) return;
    const int j  = h - 256;
    const int tl = threadIdx.x >> 3;
    const int il = (threadIdx.x & 7) * 4;
    const int t  = c * 32 + tl;
    const int i  = j * 32 + il;

    wait_cnt(&g_scnt[c], SCAN_BLOCKS);

    uint2 kb = g_kb[t];
    const size_t base = (size_t)t * N_NEUR + i;
    float4 xv = __ldcg(reinterpret_cast<const float4*>(out + base));
    const float RDT = 0.003f;                 // rate * dt
    float xs[4] = {xv.x, xv.y, xv.z, xv.w};
    float sv[4];
#pragma unroll
    for (int jx = 0; jx < 4; jx++) {
      uint2 r  = threefry2x32(kb.x, kb.y, 0u, (uint32_t)(i + jx), one);
      float u  = u01_from_bits(r.x ^ r.y);
      float pr = __fadd_rn(RDT, xs[jx]);
      pr = fminf(fmaxf(pr, 0.0f), 1.0f);      // jnp.clip
      sv[jx] = (u < pr) ? 1.0f : 0.0f;
    }
    float4 s; s.x = sv[0]; s.y = sv[1]; s.z = sv[2]; s.w = sv[3];
    *reinterpret_cast<float4*>(out + base) = s;
  }
}

// ---------------------------------------------------------------------------
// launch
// ---------------------------------------------------------------------------
extern "C" void kernel_launch(void* const* d_in, const int* in_sizes, int n_in,
                              void* d_out, int out_size) {
  const float* state = (const float*)d_in[0];   // zeros [N]
  float* out = (float*)d_out;                   // f32 [T*N]

  k_keys<<<T_STEPS / 256, 256>>>();
  // 256 scan blocks + 514 groups x 512 (noise | spike, lag 2)
  k_mega<<<SCAN_BLOCKS + (NCHUNK + 2) * 512, 256>>>(state, out);
}

// round 10
// speedup vs baseline: 2.5213x; 2.5213x over previous
#include <cuda_runtime.h>
#include <cstdint>
#include <math.h>

// Pacemaker: OU process + Bernoulli spikes, bit-matching JAX threefry2x32
// (partitionable/fold-like semantics) + XLA erfinv.
// T=16384 steps, N=8192 neurons, out = f32 spikes [T, N].
//
// R9 = R7 skeleton (best: 1501us) + threefry round-adds moved to the FMA pipe
// via IMAD with a runtime-opaque multiplier (alu pipe was the measured
// bottleneck: k_spike alu=93% fma=26%), + scan prefetch depth 3.

#define T_STEPS 16384
#define N_NEUR  8192

__device__ uint2 g_kn[T_STEPS];
__device__ uint2 g_kb[T_STEPS];
// noise, T-MAJOR: g_noise[t * N_NEUR + i]
__device__ __align__(16) float g_noise[(size_t)T_STEPS * N_NEUR];
__device__ uint32_t g_one;     // runtime 1; opaque so IMAD survives ptxas

// ---------------------------------------------------------------------------
// threefry2x32 (20 rounds) — identical to jax._src.prng.threefry2x32.
// Round adds emitted as IMAD (fma pipe): x0 = x1*one + x0  (one == 1).
// ---------------------------------------------------------------------------
__device__ __forceinline__ uint32_t addx(uint32_t a, uint32_t b, uint32_t one) {
  uint32_t r;
  asm("mad.lo.u32 %0, %1, %2, %3;" : "=r"(r) : "r"(a), "r"(one), "r"(b));
  return r;
}

__device__ __forceinline__ void tf_round4(uint32_t& x0, uint32_t& x1,
                                          int r0, int r1, int r2, int r3,
                                          uint32_t one) {
  x0 = addx(x0, x1, one); x1 = __funnelshift_l(x1, x1, r0); x1 ^= x0;
  x0 = addx(x0, x1, one); x1 = __funnelshift_l(x1, x1, r1); x1 ^= x0;
  x0 = addx(x0, x1, one); x1 = __funnelshift_l(x1, x1, r2); x1 ^= x0;
  x0 = addx(x0, x1, one); x1 = __funnelshift_l(x1, x1, r3); x1 ^= x0;
}

__device__ __forceinline__ uint2 threefry2x32(uint32_t k0, uint32_t k1,
                                              uint32_t x0, uint32_t x1,
                                              uint32_t one) {
  uint32_t ks2 = k0 ^ k1 ^ 0x1BD11BDAu;
  x0 += k0; x1 += k1;
  tf_round4(x0, x1, 13, 15, 26, 6,  one); x0 += k1;  x1 += ks2 + 1u;
  tf_round4(x0, x1, 17, 29, 16, 24, one); x0 += ks2; x1 += k0  + 2u;
  tf_round4(x0, x1, 13, 15, 26, 6,  one); x0 += k0;  x1 += k1  + 3u;
  tf_round4(x0, x1, 17, 29, 16, 24, one); x0 += k1;  x1 += ks2 + 4u;
  tf_round4(x0, x1, 13, 15, 26, 6,  one); x0 += ks2; x1 += k0  + 5u;
  return make_uint2(x0, x1);
}

// uniform [0,1): bitcast((bits>>9)|0x3f800000) - 1  (exact, matches jax)
__device__ __forceinline__ float u01_from_bits(uint32_t bits) {
  return __fsub_rn(__uint_as_float((bits >> 9) | 0x3f800000u), 1.0f);
}

// ---------------------------------------------------------------------------
// XLA ErfInv (f32, Giles). Separate mul/add (XLA does not form FMAs).
// ---------------------------------------------------------------------------
__device__ __forceinline__ float erfinv_xla(float x) {
  float w = -log1pf(-__fmul_rn(x, x));
  float p;
  if (w < 5.0f) {
    w = __fadd_rn(w, -2.5f);
    p = 2.81022636e-08f;
    p = __fadd_rn(3.43273939e-07f,  __fmul_rn(p, w));
    p = __fadd_rn(-3.5233877e-06f,  __fmul_rn(p, w));
    p = __fadd_rn(-4.39150654e-06f, __fmul_rn(p, w));
    p = __fadd_rn(0.00021858087f,   __fmul_rn(p, w));
    p = __fadd_rn(-0.00125372503f,  __fmul_rn(p, w));
    p = __fadd_rn(-0.00417768164f,  __fmul_rn(p, w));
    p = __fadd_rn(0.246640727f,     __fmul_rn(p, w));
    p = __fadd_rn(1.50140941f,      __fmul_rn(p, w));
  } else {
    w = __fadd_rn(__fsqrt_rn(w), -3.0f);
    p = -0.000200214257f;
    p = __fadd_rn(0.000100950558f,  __fmul_rn(p, w));
    p = __fadd_rn(0.00134934322f,   __fmul_rn(p, w));
    p = __fadd_rn(-0.00367342844f,  __fmul_rn(p, w));
    p = __fadd_rn(0.00573950773f,   __fmul_rn(p, w));
    p = __fadd_rn(-0.0076224613f,   __fmul_rn(p, w));
    p = __fadd_rn(0.00943887047f,   __fmul_rn(p, w));
    p = __fadd_rn(1.00167406f,      __fmul_rn(p, w));
    p = __fadd_rn(2.83297682f,      __fmul_rn(p, w));
  }
  return __fmul_rn(p, x);
}

// ---------------------------------------------------------------------------
// K0: per-step keys (and publish g_one).
// split(key(0),T)[t] = TF((0,0),(0,t)); kn = TF(kt,(0,0)); kb = TF(kt,(0,1))
// ---------------------------------------------------------------------------
__global__ void __launch_bounds__(256) k_keys() {
  int t = blockIdx.x * blockDim.x + threadIdx.x;
  if (t == 0) g_one = 1u;
  if (t >= T_STEPS) return;
  uint2 kt = threefry2x32(0u, 0u, 0u, (uint32_t)t, 1u);
  g_kn[t] = threefry2x32(kt.x, kt.y, 0u, 0u, 1u);
  g_kb[t] = threefry2x32(kt.x, kt.y, 0u, 1u, 1u);
}

// ---------------------------------------------------------------------------
// K1: noise gen, T-MAJOR output. Block = 8 warps; warp owns one t (kn_t
// warp-uniform). Lane handles 4 consecutive neurons -> coalesced STG.128.
// bits(t,i) = TF(kn_t, (0, i)).x ^ .y
// ---------------------------------------------------------------------------
__global__ void __launch_bounds__(256) k_noise() {
  const int IB = N_NEUR / 128;                 // 64 i-groups of 128 neurons
  const unsigned b = blockIdx.x;
  const int ib = (int)(b % IB);
  const int tb = (int)(b / IB);

  const int warp = threadIdx.x >> 5;
  const int lane = threadIdx.x & 31;
  const int t  = tb * 8 + warp;
  const int i0 = ib * 128 + lane * 4;

  const uint32_t one = g_one;
  uint2 kn = g_kn[t];                          // warp-uniform

  const float LO  = __uint_as_float(0xBF7FFFFFu);   // nextafter(-1, 0)
  const float SQ2 = __uint_as_float(0x3FB504F3u);   // float(sqrt(2))
  const float NS  = (float)(0.6 * sqrt(0.001));     // sigma * sqrt(dt)

  float tmp[4];
#pragma unroll
  for (int j = 0; j < 4; j++) {
    uint2 r = threefry2x32(kn.x, kn.y, 0u, (uint32_t)(i0 + j), one);
    float f = u01_from_bits(r.x ^ r.y);
    float u = __fadd_rn(__fmul_rn(f, 2.0f), LO);
    u = fmaxf(LO, u);
    tmp[j] = __fmul_rn(__fmul_rn(SQ2, erfinv_xla(u)), NS);
  }
  float4 o; o.x = tmp[0]; o.y = tmp[1]; o.z = tmp[2]; o.w = tmp[3];
  *reinterpret_cast<float4*>(g_noise + (size_t)t * N_NEUR + i0) = o;
}

// ---------------------------------------------------------------------------
// K2: serial OU scan (exact FP order). Thread = neuron, lane = consecutive i
// -> every LDG.32/STG.32 is one 128B line per warp. Scalar triple-buffer,
// prefetch distance 3 chunks (96 loads in flight per thread-group window).
// Writes x t-major into d_out (spike pass rewrites in place).
// ---------------------------------------------------------------------------
__global__ void __launch_bounds__(32) k_scan(const float* __restrict__ state,
                                             float* __restrict__ xo) {
  const int i = blockIdx.x * 32 + threadIdx.x;
  float x = state[i];
  const float DT_F = 0.001f;
  const int NCH = T_STEPS / 32;                // 512 chunks of 32 steps

  const float* __restrict__ src = g_noise + i;
  float b0[32], b1[32], b2[32];

#pragma unroll
  for (int k = 0; k < 32; k++) b0[k] = __ldcs(src + (size_t)k * N_NEUR);
#pragma unroll
  for (int k = 0; k < 32; k++) b1[k] = __ldcs(src + (size_t)(32 + k) * N_NEUR);
#pragma unroll
  for (int k = 0; k < 32; k++) b2[k] = __ldcs(src + (size_t)(64 + k) * N_NEUR);

  for (int c = 0; c < NCH; c++) {
    int pc = c + 3; if (pc > NCH - 1) pc = NCH - 1;
    const float* ps = src + (size_t)pc * 32 * N_NEUR;
    float pf[32];
#pragma unroll
    for (int k = 0; k < 32; k++) pf[k] = __ldcs(ps + (size_t)k * N_NEUR);

    float* dst = xo + (size_t)c * 32 * N_NEUR + i;
#pragma unroll
    for (int k = 0; k < 32; k++) {
      x = __fadd_rn(__fsub_rn(x, __fmul_rn(x, DT_F)), b0[k]);
      dst[(size_t)k * N_NEUR] = x;
    }
#pragma unroll
    for (int k = 0; k < 32; k++) { b0[k] = b1[k]; b1[k] = b2[k]; b2[k] = pf[k]; }
  }
}

// ---------------------------------------------------------------------------
// K3: spikes. Thread = 4 consecutive neurons at one t; in-place on d_out.
// u = TF(kb_t, (0,i)).x ^ .y
// ---------------------------------------------------------------------------
__global__ void __launch_bounds__(256) k_spike(float* __restrict__ xo) {
  unsigned tid = blockIdx.x * 256u + threadIdx.x;
  unsigned t   = tid / (N_NEUR / 4);
  unsigned i0  = (tid % (N_NEUR / 4)) * 4u;
  const uint32_t one = g_one;
  uint2 kb = g_kb[t];
  size_t base = (size_t)t * N_NEUR + i0;

  float4 xv = *reinterpret_cast<const float4*>(xo + base);
  const float RDT = 0.003f;   // rate * dt
  float xs[4] = {xv.x, xv.y, xv.z, xv.w};
  float sv[4];
#pragma unroll
  for (int j = 0; j < 4; j++) {
    uint2 r  = threefry2x32(kb.x, kb.y, 0u, i0 + (unsigned)j, one);
    float u  = u01_from_bits(r.x ^ r.y);
    float pr = __fadd_rn(RDT, xs[j]);
    pr = fminf(fmaxf(pr, 0.0f), 1.0f);   // jnp.clip
    sv[j] = (u < pr) ? 1.0f : 0.0f;
  }
  float4 s; s.x = sv[0]; s.y = sv[1]; s.z = sv[2]; s.w = sv[3];
  *reinterpret_cast<float4*>(xo + base) = s;
}

// ---------------------------------------------------------------------------
// launch
// ---------------------------------------------------------------------------
extern "C" void kernel_launch(void* const* d_in, const int* in_sizes, int n_in,
                              void* d_out, int out_size) {
  const float* state = (const float*)d_in[0];   // zeros [N]
  float* out = (float*)d_out;                   // f32 [T*N]

  k_keys <<<T_STEPS / 256, 256>>>();
  k_noise<<<(N_NEUR / 128) * (T_STEPS / 8), 256>>>();
  k_scan <<<N_NEUR / 32, 32>>>(state, out);
  k_spike<<<(unsigned)((size_t)T_STEPS * N_NEUR / 4 / 256), 256>>>(out);
}